// round 1
// baseline (speedup 1.0000x reference)
#include <cuda_runtime.h>
#include <math.h>

#define EDIM 512
#define HDIM 64
#define NH   8
#define BATCH 4
#define SEQ  2048
#define MROWS (BATCH*SEQ)   // 8192
#define FFN  2048

// ---------------- scratch (no cudaMalloc allowed) ----------------
__device__ float g_q[MROWS*EDIM];
__device__ float g_k[MROWS*EDIM];
__device__ float g_v[MROWS*EDIM];
__device__ float g_ctx[MROWS*EDIM];
__device__ float g_tmp[MROWS*EDIM];
__device__ float g_ln1[MROWS*EDIM];
__device__ float g_h[MROWS*FFN];

// ---------------- generic tiled GEMM: C = A[M,K]@W[K,N] + bias (opt GELU) ----
template<int DO_GELU>
__global__ void __launch_bounds__(256) gemm_kernel(
    const float* __restrict__ A, const float* __restrict__ W,
    const float* __restrict__ bias, float* __restrict__ C,
    int M, int N, int K)
{
    __shared__ float As[64*17];   // padded: stride 17 kills bank conflicts
    __shared__ float Ws[16*64];

    const int tid = threadIdx.x;
    const int tx = tid & 15, ty = tid >> 4;
    const int n0 = blockIdx.x * 64, m0 = blockIdx.y * 64;

    float acc[4][4] = {};

    const int ar = tid >> 2,  ac = (tid & 3)  * 4;   // A-tile loader: 64x16
    const int wr = tid >> 4,  wc = (tid & 15) * 4;   // W-tile loader: 16x64
    const float* Aptr = A + (size_t)(m0 + ar) * K + ac;
    const float* Wptr = W + (size_t)wr * N + n0 + wc;

    for (int kt = 0; kt < K; kt += 16) {
        float4 av = *(const float4*)(Aptr + kt);
        As[ar*17 + ac + 0] = av.x;
        As[ar*17 + ac + 1] = av.y;
        As[ar*17 + ac + 2] = av.z;
        As[ar*17 + ac + 3] = av.w;
        *(float4*)&Ws[wr*64 + wc] = *(const float4*)(Wptr + (size_t)kt * N);
        __syncthreads();

        #pragma unroll
        for (int k = 0; k < 16; k++) {
            float a0 = As[(ty*4+0)*17 + k];
            float a1 = As[(ty*4+1)*17 + k];
            float a2 = As[(ty*4+2)*17 + k];
            float a3 = As[(ty*4+3)*17 + k];
            float4 wv = *(const float4*)&Ws[k*64 + tx*4];
            acc[0][0] += a0*wv.x; acc[0][1] += a0*wv.y; acc[0][2] += a0*wv.z; acc[0][3] += a0*wv.w;
            acc[1][0] += a1*wv.x; acc[1][1] += a1*wv.y; acc[1][2] += a1*wv.z; acc[1][3] += a1*wv.w;
            acc[2][0] += a2*wv.x; acc[2][1] += a2*wv.y; acc[2][2] += a2*wv.z; acc[2][3] += a2*wv.w;
            acc[3][0] += a3*wv.x; acc[3][1] += a3*wv.y; acc[3][2] += a3*wv.z; acc[3][3] += a3*wv.w;
        }
        __syncthreads();
    }

    const float b0 = bias[n0 + tx*4 + 0];
    const float b1 = bias[n0 + tx*4 + 1];
    const float b2 = bias[n0 + tx*4 + 2];
    const float b3 = bias[n0 + tx*4 + 3];
    #pragma unroll
    for (int ii = 0; ii < 4; ii++) {
        float v0 = acc[ii][0] + b0;
        float v1 = acc[ii][1] + b1;
        float v2 = acc[ii][2] + b2;
        float v3 = acc[ii][3] + b3;
        if (DO_GELU) {
            v0 = 0.5f*v0*(1.0f + erff(v0*0.70710678118654752f));
            v1 = 0.5f*v1*(1.0f + erff(v1*0.70710678118654752f));
            v2 = 0.5f*v2*(1.0f + erff(v2*0.70710678118654752f));
            v3 = 0.5f*v3*(1.0f + erff(v3*0.70710678118654752f));
        }
        *(float4*)(C + (size_t)(m0 + ty*4 + ii) * N + n0 + tx*4) =
            make_float4(v0, v1, v2, v3);
    }
}

// ---------------- flash attention: per (b, h, 64-query tile) -----------------
__global__ void __launch_bounds__(256) attn_kernel(
    const float* __restrict__ Q, const float* __restrict__ K,
    const float* __restrict__ V, float* __restrict__ O)
{
    __shared__ float Qs[64*64];    // [row][d]
    __shared__ float KPs[64*64];   // K^T [d][j], then reused as P [row][j]
    __shared__ float Vs[64*64];    // [j][d]

    const int tid = threadIdx.x;
    const int tx = tid & 15, ty = tid >> 4;
    const int qt = blockIdx.x, h = blockIdx.y, b = blockIdx.z;

    const size_t baseq  = ((size_t)(b*SEQ + qt*64)) * EDIM + h*HDIM;
    const size_t basekv = ((size_t)(b*SEQ)) * EDIM + h*HDIM;

    // load Q tile scaled by 1/sqrt(Dh)
    #pragma unroll
    for (int i = 0; i < 4; i++) {
        int fi = tid + i*256;
        int r = fi >> 4, c = (fi & 15) * 4;
        float4 v = *(const float4*)(Q + baseq + (size_t)r*EDIM + c);
        v.x *= 0.125f; v.y *= 0.125f; v.z *= 0.125f; v.w *= 0.125f;
        *(float4*)&Qs[r*64 + c] = v;
    }

    float m[4], l[4], o[4][4];
    #pragma unroll
    for (int ii = 0; ii < 4; ii++) {
        m[ii] = -INFINITY; l[ii] = 0.0f;
        #pragma unroll
        for (int jj = 0; jj < 4; jj++) o[ii][jj] = 0.0f;
    }
    const int r0 = ty*4, c0 = tx*4;

    for (int kt2 = 0; kt2 < SEQ/64; kt2++) {
        __syncthreads();  // protect KPs/Vs from previous iteration readers
        #pragma unroll
        for (int i = 0; i < 4; i++) {
            int fi = tid + i*256;
            int j = fi >> 4, d = (fi & 15) * 4;
            float4 kv = *(const float4*)(K + basekv + (size_t)(kt2*64 + j)*EDIM + d);
            KPs[(d+0)*64 + j] = kv.x;
            KPs[(d+1)*64 + j] = kv.y;
            KPs[(d+2)*64 + j] = kv.z;
            KPs[(d+3)*64 + j] = kv.w;
            *(float4*)&Vs[j*64 + d] =
                *(const float4*)(V + basekv + (size_t)(kt2*64 + j)*EDIM + d);
        }
        __syncthreads();

        // scores S = Qs @ K^T  (4x4 per thread)
        float s[4][4] = {};
        #pragma unroll
        for (int d = 0; d < 64; d += 4) {
            float qa[4][4];
            #pragma unroll
            for (int ii = 0; ii < 4; ii++)
                *(float4*)&qa[ii][0] = *(const float4*)&Qs[(r0+ii)*64 + d];
            #pragma unroll
            for (int u = 0; u < 4; u++) {
                float4 kk = *(const float4*)&KPs[(d+u)*64 + c0];
                #pragma unroll
                for (int ii = 0; ii < 4; ii++) {
                    s[ii][0] += qa[ii][u]*kk.x;
                    s[ii][1] += qa[ii][u]*kk.y;
                    s[ii][2] += qa[ii][u]*kk.z;
                    s[ii][3] += qa[ii][u]*kk.w;
                }
            }
        }

        // online softmax (row spread over 16 tx threads; shfl within half-warp)
        #pragma unroll
        for (int ii = 0; ii < 4; ii++) {
            float mx = fmaxf(fmaxf(s[ii][0], s[ii][1]), fmaxf(s[ii][2], s[ii][3]));
            #pragma unroll
            for (int off = 1; off < 16; off <<= 1)
                mx = fmaxf(mx, __shfl_xor_sync(0xffffffffu, mx, off));
            float mnew = fmaxf(m[ii], mx);
            float alpha = __expf(m[ii] - mnew);
            float psum = 0.0f;
            #pragma unroll
            for (int jj = 0; jj < 4; jj++) {
                s[ii][jj] = __expf(s[ii][jj] - mnew);
                psum += s[ii][jj];
            }
            #pragma unroll
            for (int off = 1; off < 16; off <<= 1)
                psum += __shfl_xor_sync(0xffffffffu, psum, off);
            l[ii] = l[ii]*alpha + psum;
            m[ii] = mnew;
            #pragma unroll
            for (int jj = 0; jj < 4; jj++) o[ii][jj] *= alpha;
        }

        __syncthreads();  // all score reads of KPs done -> reuse as P
        #pragma unroll
        for (int ii = 0; ii < 4; ii++)
            *(float4*)&KPs[(r0+ii)*64 + c0] =
                make_float4(s[ii][0], s[ii][1], s[ii][2], s[ii][3]);
        __syncthreads();

        // O += P @ V
        #pragma unroll
        for (int j = 0; j < 64; j += 4) {
            float pa[4][4];
            #pragma unroll
            for (int ii = 0; ii < 4; ii++)
                *(float4*)&pa[ii][0] = *(const float4*)&KPs[(r0+ii)*64 + j];
            #pragma unroll
            for (int u = 0; u < 4; u++) {
                float4 vv = *(const float4*)&Vs[(j+u)*64 + c0];
                #pragma unroll
                for (int ii = 0; ii < 4; ii++) {
                    o[ii][0] += pa[ii][u]*vv.x;
                    o[ii][1] += pa[ii][u]*vv.y;
                    o[ii][2] += pa[ii][u]*vv.z;
                    o[ii][3] += pa[ii][u]*vv.w;
                }
            }
        }
    }

    #pragma unroll
    for (int ii = 0; ii < 4; ii++) {
        float inv = 1.0f / l[ii];
        *(float4*)(O + baseq + (size_t)(r0+ii)*EDIM + c0) =
            make_float4(o[ii][0]*inv, o[ii][1]*inv, o[ii][2]*inv, o[ii][3]*inv);
    }
}

// ---------------- fused residual + LayerNorm -------------------------------
__global__ void __launch_bounds__(128) ln_kernel(
    const float* __restrict__ X, const float* __restrict__ Y,
    const float* __restrict__ gamma, const float* __restrict__ beta,
    float* __restrict__ out)
{
    const int row = blockIdx.x;
    const int tid = threadIdx.x;
    const int lane = tid & 31, w = tid >> 5;

    float4 xv = *(const float4*)(X + (size_t)row*EDIM + tid*4);
    float4 yv = *(const float4*)(Y + (size_t)row*EDIM + tid*4);
    float v0 = xv.x + yv.x, v1 = xv.y + yv.y, v2 = xv.z + yv.z, v3 = xv.w + yv.w;

    float sum = v0 + v1 + v2 + v3;
    float sq  = v0*v0 + v1*v1 + v2*v2 + v3*v3;
    #pragma unroll
    for (int off = 16; off > 0; off >>= 1) {
        sum += __shfl_xor_sync(0xffffffffu, sum, off);
        sq  += __shfl_xor_sync(0xffffffffu, sq, off);
    }
    __shared__ float ssum[4], ssq[4];
    if (lane == 0) { ssum[w] = sum; ssq[w] = sq; }
    __syncthreads();
    float ts = ssum[0] + ssum[1] + ssum[2] + ssum[3];
    float tq = ssq[0] + ssq[1] + ssq[2] + ssq[3];

    float mu   = ts * (1.0f/EDIM);
    float var  = tq * (1.0f/EDIM) - mu*mu;
    float rstd = rsqrtf(var + 1e-5f);

    float4 gv = *(const float4*)(gamma + tid*4);
    float4 bv = *(const float4*)(beta  + tid*4);
    float4 ov;
    ov.x = (v0 - mu)*rstd*gv.x + bv.x;
    ov.y = (v1 - mu)*rstd*gv.y + bv.y;
    ov.z = (v2 - mu)*rstd*gv.z + bv.z;
    ov.w = (v3 - mu)*rstd*gv.w + bv.w;
    *(float4*)(out + (size_t)row*EDIM + tid*4) = ov;
}

// ---------------- launch ----------------------------------------------------
extern "C" void kernel_launch(void* const* d_in, const int* in_sizes, int n_in,
                              void* d_out, int out_size)
{
    const float* query = (const float*)d_in[0];
    const float* key   = (const float*)d_in[1];
    const float* value = (const float*)d_in[2];
    const float* Wq = (const float*)d_in[3];  const float* bq = (const float*)d_in[4];
    const float* Wk = (const float*)d_in[5];  const float* bk = (const float*)d_in[6];
    const float* Wv = (const float*)d_in[7];  const float* bv = (const float*)d_in[8];
    const float* Wo = (const float*)d_in[9];  const float* bo = (const float*)d_in[10];
    const float* g1 = (const float*)d_in[11]; const float* be1 = (const float*)d_in[12];
    const float* g2 = (const float*)d_in[13]; const float* be2 = (const float*)d_in[14];
    const float* W1 = (const float*)d_in[15]; const float* b1 = (const float*)d_in[16];
    const float* W2 = (const float*)d_in[17]; const float* b2 = (const float*)d_in[18];
    float* out = (float*)d_out;

    float *q, *k, *v, *ctx, *tmp, *ln1, *hbuf;
    cudaGetSymbolAddress((void**)&q,    g_q);
    cudaGetSymbolAddress((void**)&k,    g_k);
    cudaGetSymbolAddress((void**)&v,    g_v);
    cudaGetSymbolAddress((void**)&ctx,  g_ctx);
    cudaGetSymbolAddress((void**)&tmp,  g_tmp);
    cudaGetSymbolAddress((void**)&ln1,  g_ln1);
    cudaGetSymbolAddress((void**)&hbuf, g_h);

    dim3 gProj(EDIM/64, MROWS/64);      // 8 x 128
    dim3 gF1(FFN/64,  MROWS/64);        // 32 x 128

    gemm_kernel<0><<<gProj, 256>>>(query, Wq, bq, q, MROWS, EDIM, EDIM);
    gemm_kernel<0><<<gProj, 256>>>(key,   Wk, bk, k, MROWS, EDIM, EDIM);
    gemm_kernel<0><<<gProj, 256>>>(value, Wv, bv, v, MROWS, EDIM, EDIM);

    attn_kernel<<<dim3(SEQ/64, NH, BATCH), 256>>>(q, k, v, ctx);

    gemm_kernel<0><<<gProj, 256>>>(ctx, Wo, bo, tmp, MROWS, EDIM, EDIM);
    ln_kernel<<<MROWS, 128>>>(query, tmp, g1, be1, ln1);

    gemm_kernel<1><<<gF1, 256>>>(ln1, W1, b1, hbuf, MROWS, FFN, EDIM);
    gemm_kernel<0><<<gProj, 256>>>(hbuf, W2, b2, tmp, MROWS, EDIM, FFN);
    ln_kernel<<<MROWS, 128>>>(ln1, tmp, g2, be2, out);
}

// round 2
// speedup vs baseline: 1.5070x; 1.5070x over previous
#include <cuda_runtime.h>
#include <math.h>

#define EDIM 512
#define HDIM 64
#define NH   8
#define BATCH 4
#define SEQ  2048
#define MROWS (BATCH*SEQ)   // 8192
#define FFN  2048

// ---------------- scratch (no cudaMalloc allowed) ----------------
__device__ float g_q[MROWS*EDIM];
__device__ float g_k[MROWS*EDIM];
__device__ float g_v[MROWS*EDIM];
__device__ float g_ctx[MROWS*EDIM];
__device__ float g_tmp[MROWS*EDIM];
__device__ float g_ln1[MROWS*EDIM];
__device__ float g_h[MROWS*FFN];

// =================== TF32 tensor-core GEMM ===================
// C[M,N] = A[M,K] @ W[K,N] + bias, optional exact GELU.
// Block tile 128x64x32, 256 threads = 8 warps (4m x 2n), warp tile 32x32.
#define BM 128
#define BN 64
#define BK 32
#define ASTR 36   // (g*36+tig)%32 = g*4+tig -> conflict-free A frags
#define BSTR 72   // (tig*72+g)%32 = tig*8+g -> conflict-free B frags

__device__ __forceinline__ float to_tf32(float x) {
    unsigned u;
    asm("cvt.rna.tf32.f32 %0, %1;" : "=r"(u) : "f"(x));
    return __uint_as_float(u);
}

__device__ __forceinline__ void mma_tf32(float d[4],
                                         const unsigned a[4],
                                         const unsigned b[2]) {
    asm volatile(
        "mma.sync.aligned.m16n8k8.row.col.f32.tf32.tf32.f32 "
        "{%0,%1,%2,%3}, {%4,%5,%6,%7}, {%8,%9}, {%0,%1,%2,%3};\n"
        : "+f"(d[0]), "+f"(d[1]), "+f"(d[2]), "+f"(d[3])
        : "r"(a[0]), "r"(a[1]), "r"(a[2]), "r"(a[3]),
          "r"(b[0]), "r"(b[1]));
}

template<int DO_GELU>
__global__ void __launch_bounds__(256) gemm_tc(
    const float* __restrict__ A, const float* __restrict__ W,
    const float* __restrict__ bias, float* __restrict__ C,
    int M, int N, int K)
{
    __shared__ float As[BM * ASTR];   // 18432 B
    __shared__ float Bs[BK * BSTR];   //  9216 B

    const int tid  = threadIdx.x;
    const int wid  = tid >> 5, lane = tid & 31;
    const int g    = lane >> 2, tig = lane & 3;
    const int wm   = wid >> 1,  wn  = wid & 1;
    const int mwb  = wm * 32,   nwb = wn * 32;
    const int bm0  = blockIdx.y * BM, bn0 = blockIdx.x * BN;

    float d[2][4][4] = {};

    // global loaders
    const int am = tid >> 3,  ak = (tid & 7) * 4;    // A: 32 rows per i-step
    const int bk = tid >> 4,  bn = (tid & 15) * 4;   // B: 16 rows per i-step
    const float* Ag = A + (size_t)(bm0 + am) * K + ak;
    const float* Wg = W + (size_t)bk * N + bn0 + bn;

    float4 aR[4], bR[2];
    const int nkt = K / BK;

    // prologue: fetch tile 0
    #pragma unroll
    for (int i = 0; i < 4; i++)
        aR[i] = *(const float4*)(Ag + (size_t)(i*32) * K);
    #pragma unroll
    for (int i = 0; i < 2; i++)
        bR[i] = *(const float4*)(Wg + (size_t)(i*16) * N);

    for (int kt = 0; kt < nkt; kt++) {
        if (kt > 0) __syncthreads();
        // store (tf32-rounded) into smem
        #pragma unroll
        for (int i = 0; i < 4; i++) {
            float4 v = aR[i];
            *(float4*)&As[(am + i*32)*ASTR + ak] =
                make_float4(to_tf32(v.x), to_tf32(v.y), to_tf32(v.z), to_tf32(v.w));
        }
        #pragma unroll
        for (int i = 0; i < 2; i++) {
            float4 v = bR[i];
            *(float4*)&Bs[(bk + i*16)*BSTR + bn] =
                make_float4(to_tf32(v.x), to_tf32(v.y), to_tf32(v.z), to_tf32(v.w));
        }
        __syncthreads();

        // prefetch next tile while computing
        if (kt + 1 < nkt) {
            #pragma unroll
            for (int i = 0; i < 4; i++)
                aR[i] = *(const float4*)(Ag + (size_t)(i*32) * K + (kt+1)*BK);
            #pragma unroll
            for (int i = 0; i < 2; i++)
                bR[i] = *(const float4*)(Wg + (size_t)((kt+1)*BK + i*16) * N);
        }

        // 4 k8 steps
        #pragma unroll
        for (int ks = 0; ks < 4; ks++) {
            unsigned a[2][4];
            #pragma unroll
            for (int mt = 0; mt < 2; mt++) {
                const float* ap = &As[(mwb + mt*16 + g)*ASTR + ks*8 + tig];
                a[mt][0] = __float_as_uint(ap[0]);
                a[mt][1] = __float_as_uint(ap[8*ASTR]);
                a[mt][2] = __float_as_uint(ap[4]);
                a[mt][3] = __float_as_uint(ap[8*ASTR + 4]);
            }
            unsigned b[4][2];
            #pragma unroll
            for (int nt = 0; nt < 4; nt++) {
                const float* bp = &Bs[(ks*8 + tig)*BSTR + nwb + nt*8 + g];
                b[nt][0] = __float_as_uint(bp[0]);
                b[nt][1] = __float_as_uint(bp[4*BSTR]);
            }
            #pragma unroll
            for (int mt = 0; mt < 2; mt++)
                #pragma unroll
                for (int nt = 0; nt < 4; nt++)
                    mma_tf32(d[mt][nt], a[mt], b[nt]);
        }
    }

    // epilogue: bias (+ GELU) and store
    #pragma unroll
    for (int mt = 0; mt < 2; mt++) {
        #pragma unroll
        for (int nt = 0; nt < 4; nt++) {
            const int col  = bn0 + nwb + nt*8 + tig*2;
            const float b0 = bias[col], b1 = bias[col + 1];
            const int row0 = bm0 + mwb + mt*16 + g;
            float v0 = d[mt][nt][0] + b0;
            float v1 = d[mt][nt][1] + b1;
            float v2 = d[mt][nt][2] + b0;
            float v3 = d[mt][nt][3] + b1;
            if (DO_GELU) {
                v0 = 0.5f*v0*(1.0f + erff(v0*0.70710678118654752f));
                v1 = 0.5f*v1*(1.0f + erff(v1*0.70710678118654752f));
                v2 = 0.5f*v2*(1.0f + erff(v2*0.70710678118654752f));
                v3 = 0.5f*v3*(1.0f + erff(v3*0.70710678118654752f));
            }
            *(float2*)(C + (size_t)row0 * N + col)       = make_float2(v0, v1);
            *(float2*)(C + (size_t)(row0 + 8) * N + col) = make_float2(v2, v3);
        }
    }
}

// ---------------- flash attention: per (b, h, 64-query tile) -----------------
__global__ void __launch_bounds__(256) attn_kernel(
    const float* __restrict__ Q, const float* __restrict__ K,
    const float* __restrict__ V, float* __restrict__ O)
{
    __shared__ float Qs[64*64];    // [row][d]
    __shared__ float KPs[64*64];   // K^T [d][j], then reused as P [row][j]
    __shared__ float Vs[64*64];    // [j][d]

    const int tid = threadIdx.x;
    const int tx = tid & 15, ty = tid >> 4;
    const int qt = blockIdx.x, h = blockIdx.y, b = blockIdx.z;

    const size_t baseq  = ((size_t)(b*SEQ + qt*64)) * EDIM + h*HDIM;
    const size_t basekv = ((size_t)(b*SEQ)) * EDIM + h*HDIM;

    #pragma unroll
    for (int i = 0; i < 4; i++) {
        int fi = tid + i*256;
        int r = fi >> 4, c = (fi & 15) * 4;
        float4 v = *(const float4*)(Q + baseq + (size_t)r*EDIM + c);
        v.x *= 0.125f; v.y *= 0.125f; v.z *= 0.125f; v.w *= 0.125f;
        *(float4*)&Qs[r*64 + c] = v;
    }

    float m[4], l[4], o[4][4];
    #pragma unroll
    for (int ii = 0; ii < 4; ii++) {
        m[ii] = -INFINITY; l[ii] = 0.0f;
        #pragma unroll
        for (int jj = 0; jj < 4; jj++) o[ii][jj] = 0.0f;
    }
    const int r0 = ty*4, c0 = tx*4;

    for (int kt2 = 0; kt2 < SEQ/64; kt2++) {
        __syncthreads();
        #pragma unroll
        for (int i = 0; i < 4; i++) {
            int fi = tid + i*256;
            int j = fi >> 4, d = (fi & 15) * 4;
            float4 kv = *(const float4*)(K + basekv + (size_t)(kt2*64 + j)*EDIM + d);
            KPs[(d+0)*64 + j] = kv.x;
            KPs[(d+1)*64 + j] = kv.y;
            KPs[(d+2)*64 + j] = kv.z;
            KPs[(d+3)*64 + j] = kv.w;
            *(float4*)&Vs[j*64 + d] =
                *(const float4*)(V + basekv + (size_t)(kt2*64 + j)*EDIM + d);
        }
        __syncthreads();

        float s[4][4] = {};
        #pragma unroll
        for (int d = 0; d < 64; d += 4) {
            float qa[4][4];
            #pragma unroll
            for (int ii = 0; ii < 4; ii++)
                *(float4*)&qa[ii][0] = *(const float4*)&Qs[(r0+ii)*64 + d];
            #pragma unroll
            for (int u = 0; u < 4; u++) {
                float4 kk = *(const float4*)&KPs[(d+u)*64 + c0];
                #pragma unroll
                for (int ii = 0; ii < 4; ii++) {
                    s[ii][0] += qa[ii][u]*kk.x;
                    s[ii][1] += qa[ii][u]*kk.y;
                    s[ii][2] += qa[ii][u]*kk.z;
                    s[ii][3] += qa[ii][u]*kk.w;
                }
            }
        }

        #pragma unroll
        for (int ii = 0; ii < 4; ii++) {
            float mx = fmaxf(fmaxf(s[ii][0], s[ii][1]), fmaxf(s[ii][2], s[ii][3]));
            #pragma unroll
            for (int off = 1; off < 16; off <<= 1)
                mx = fmaxf(mx, __shfl_xor_sync(0xffffffffu, mx, off));
            float mnew = fmaxf(m[ii], mx);
            float alpha = __expf(m[ii] - mnew);
            float psum = 0.0f;
            #pragma unroll
            for (int jj = 0; jj < 4; jj++) {
                s[ii][jj] = __expf(s[ii][jj] - mnew);
                psum += s[ii][jj];
            }
            #pragma unroll
            for (int off = 1; off < 16; off <<= 1)
                psum += __shfl_xor_sync(0xffffffffu, psum, off);
            l[ii] = l[ii]*alpha + psum;
            m[ii] = mnew;
            #pragma unroll
            for (int jj = 0; jj < 4; jj++) o[ii][jj] *= alpha;
        }

        __syncthreads();
        #pragma unroll
        for (int ii = 0; ii < 4; ii++)
            *(float4*)&KPs[(r0+ii)*64 + c0] =
                make_float4(s[ii][0], s[ii][1], s[ii][2], s[ii][3]);
        __syncthreads();

        #pragma unroll
        for (int j = 0; j < 64; j += 4) {
            float pa[4][4];
            #pragma unroll
            for (int ii = 0; ii < 4; ii++)
                *(float4*)&pa[ii][0] = *(const float4*)&KPs[(r0+ii)*64 + j];
            #pragma unroll
            for (int u = 0; u < 4; u++) {
                float4 vv = *(const float4*)&Vs[(j+u)*64 + c0];
                #pragma unroll
                for (int ii = 0; ii < 4; ii++) {
                    o[ii][0] += pa[ii][u]*vv.x;
                    o[ii][1] += pa[ii][u]*vv.y;
                    o[ii][2] += pa[ii][u]*vv.z;
                    o[ii][3] += pa[ii][u]*vv.w;
                }
            }
        }
    }

    #pragma unroll
    for (int ii = 0; ii < 4; ii++) {
        float inv = 1.0f / l[ii];
        *(float4*)(O + baseq + (size_t)(r0+ii)*EDIM + c0) =
            make_float4(o[ii][0]*inv, o[ii][1]*inv, o[ii][2]*inv, o[ii][3]*inv);
    }
}

// ---------------- fused residual + LayerNorm -------------------------------
__global__ void __launch_bounds__(128) ln_kernel(
    const float* __restrict__ X, const float* __restrict__ Y,
    const float* __restrict__ gamma, const float* __restrict__ beta,
    float* __restrict__ out)
{
    const int row = blockIdx.x;
    const int tid = threadIdx.x;
    const int lane = tid & 31, w = tid >> 5;

    float4 xv = *(const float4*)(X + (size_t)row*EDIM + tid*4);
    float4 yv = *(const float4*)(Y + (size_t)row*EDIM + tid*4);
    float v0 = xv.x + yv.x, v1 = xv.y + yv.y, v2 = xv.z + yv.z, v3 = xv.w + yv.w;

    float sum = v0 + v1 + v2 + v3;
    float sq  = v0*v0 + v1*v1 + v2*v2 + v3*v3;
    #pragma unroll
    for (int off = 16; off > 0; off >>= 1) {
        sum += __shfl_xor_sync(0xffffffffu, sum, off);
        sq  += __shfl_xor_sync(0xffffffffu, sq, off);
    }
    __shared__ float ssum[4], ssq[4];
    if (lane == 0) { ssum[w] = sum; ssq[w] = sq; }
    __syncthreads();
    float ts = ssum[0] + ssum[1] + ssum[2] + ssum[3];
    float tq = ssq[0] + ssq[1] + ssq[2] + ssq[3];

    float mu   = ts * (1.0f/EDIM);
    float var  = tq * (1.0f/EDIM) - mu*mu;
    float rstd = rsqrtf(var + 1e-5f);

    float4 gv = *(const float4*)(gamma + tid*4);
    float4 bv = *(const float4*)(beta  + tid*4);
    float4 ov;
    ov.x = (v0 - mu)*rstd*gv.x + bv.x;
    ov.y = (v1 - mu)*rstd*gv.y + bv.y;
    ov.z = (v2 - mu)*rstd*gv.z + bv.z;
    ov.w = (v3 - mu)*rstd*gv.w + bv.w;
    *(float4*)(out + (size_t)row*EDIM + tid*4) = ov;
}

// ---------------- launch ----------------------------------------------------
extern "C" void kernel_launch(void* const* d_in, const int* in_sizes, int n_in,
                              void* d_out, int out_size)
{
    const float* query = (const float*)d_in[0];
    const float* key   = (const float*)d_in[1];
    const float* value = (const float*)d_in[2];
    const float* Wq = (const float*)d_in[3];  const float* bq = (const float*)d_in[4];
    const float* Wk = (const float*)d_in[5];  const float* bk = (const float*)d_in[6];
    const float* Wv = (const float*)d_in[7];  const float* bv = (const float*)d_in[8];
    const float* Wo = (const float*)d_in[9];  const float* bo = (const float*)d_in[10];
    const float* g1 = (const float*)d_in[11]; const float* be1 = (const float*)d_in[12];
    const float* g2 = (const float*)d_in[13]; const float* be2 = (const float*)d_in[14];
    const float* W1 = (const float*)d_in[15]; const float* b1 = (const float*)d_in[16];
    const float* W2 = (const float*)d_in[17]; const float* b2 = (const float*)d_in[18];
    float* out = (float*)d_out;

    float *q, *k, *v, *ctx, *tmp, *ln1, *hbuf;
    cudaGetSymbolAddress((void**)&q,    g_q);
    cudaGetSymbolAddress((void**)&k,    g_k);
    cudaGetSymbolAddress((void**)&v,    g_v);
    cudaGetSymbolAddress((void**)&ctx,  g_ctx);
    cudaGetSymbolAddress((void**)&tmp,  g_tmp);
    cudaGetSymbolAddress((void**)&ln1,  g_ln1);
    cudaGetSymbolAddress((void**)&hbuf, g_h);

    dim3 gProj(EDIM/BN, MROWS/BM);   // 8 x 64
    dim3 gF1(FFN/BN,  MROWS/BM);     // 32 x 64

    gemm_tc<0><<<gProj, 256>>>(query, Wq, bq, q, MROWS, EDIM, EDIM);
    gemm_tc<0><<<gProj, 256>>>(key,   Wk, bk, k, MROWS, EDIM, EDIM);
    gemm_tc<0><<<gProj, 256>>>(value, Wv, bv, v, MROWS, EDIM, EDIM);

    attn_kernel<<<dim3(SEQ/64, NH, BATCH), 256>>>(q, k, v, ctx);

    gemm_tc<0><<<gProj, 256>>>(ctx, Wo, bo, tmp, MROWS, EDIM, EDIM);
    ln_kernel<<<MROWS, 128>>>(query, tmp, g1, be1, ln1);

    gemm_tc<1><<<gF1, 256>>>(ln1, W1, b1, hbuf, MROWS, FFN, EDIM);
    gemm_tc<0><<<gProj, 256>>>(hbuf, W2, b2, tmp, MROWS, EDIM, FFN);
    ln_kernel<<<MROWS, 128>>>(ln1, tmp, g2, be2, out);
}

// round 3
// speedup vs baseline: 3.0004x; 1.9910x over previous
#include <cuda_runtime.h>
#include <math.h>

#define EDIM 512
#define HDIM 64
#define NH   8
#define BATCH 4
#define SEQ  2048
#define MROWS (BATCH*SEQ)   // 8192
#define FFN  2048

// ---------------- scratch (no cudaMalloc allowed) ----------------
__device__ float g_q[MROWS*EDIM];
__device__ float g_k[MROWS*EDIM];
__device__ float g_v[MROWS*EDIM];
__device__ float g_ctx[MROWS*EDIM];
__device__ float g_tmp[MROWS*EDIM];
__device__ float g_ln1[MROWS*EDIM];
__device__ float g_h[MROWS*FFN];

// ---------------- common helpers -------------------------------------------
__device__ __forceinline__ float to_tf32(float x) {
    unsigned u;
    asm("cvt.rna.tf32.f32 %0, %1;" : "=r"(u) : "f"(x));
    return __uint_as_float(u);
}
__device__ __forceinline__ unsigned tf32u(float x) {
    unsigned u;
    asm("cvt.rna.tf32.f32 %0, %1;" : "=r"(u) : "f"(x));
    return u;
}
__device__ __forceinline__ float ex2f(float x) {
    float y;
    asm("ex2.approx.ftz.f32 %0, %1;" : "=f"(y) : "f"(x));
    return y;
}
__device__ __forceinline__ void mma_tf32(float d[4],
                                         const unsigned a[4],
                                         const unsigned b[2]) {
    asm volatile(
        "mma.sync.aligned.m16n8k8.row.col.f32.tf32.tf32.f32 "
        "{%0,%1,%2,%3}, {%4,%5,%6,%7}, {%8,%9}, {%0,%1,%2,%3};\n"
        : "+f"(d[0]), "+f"(d[1]), "+f"(d[2]), "+f"(d[3])
        : "r"(a[0]), "r"(a[1]), "r"(a[2]), "r"(a[3]),
          "r"(b[0]), "r"(b[1]));
}

// =================== TF32 tensor-core GEMM ===================
#define BM 128
#define BN 64
#define BK 32
#define ASTR 36
#define BSTR 72

template<int DO_GELU>
__global__ void __launch_bounds__(256) gemm_tc(
    const float* __restrict__ A, const float* __restrict__ W,
    const float* __restrict__ bias, float* __restrict__ C,
    int M, int N, int K)
{
    __shared__ float As[BM * ASTR];
    __shared__ float Bs[BK * BSTR];

    const int tid  = threadIdx.x;
    const int wid  = tid >> 5, lane = tid & 31;
    const int g    = lane >> 2, tig = lane & 3;
    const int wm   = wid >> 1,  wn  = wid & 1;
    const int mwb  = wm * 32,   nwb = wn * 32;
    const int bm0  = blockIdx.y * BM, bn0 = blockIdx.x * BN;

    float d[2][4][4] = {};

    const int am = tid >> 3,  ak = (tid & 7) * 4;
    const int bk = tid >> 4,  bn = (tid & 15) * 4;
    const float* Ag = A + (size_t)(bm0 + am) * K + ak;
    const float* Wg = W + (size_t)bk * N + bn0 + bn;

    float4 aR[4], bR[2];
    const int nkt = K / BK;

    #pragma unroll
    for (int i = 0; i < 4; i++)
        aR[i] = *(const float4*)(Ag + (size_t)(i*32) * K);
    #pragma unroll
    for (int i = 0; i < 2; i++)
        bR[i] = *(const float4*)(Wg + (size_t)(i*16) * N);

    for (int kt = 0; kt < nkt; kt++) {
        if (kt > 0) __syncthreads();
        #pragma unroll
        for (int i = 0; i < 4; i++) {
            float4 v = aR[i];
            *(float4*)&As[(am + i*32)*ASTR + ak] =
                make_float4(to_tf32(v.x), to_tf32(v.y), to_tf32(v.z), to_tf32(v.w));
        }
        #pragma unroll
        for (int i = 0; i < 2; i++) {
            float4 v = bR[i];
            *(float4*)&Bs[(bk + i*16)*BSTR + bn] =
                make_float4(to_tf32(v.x), to_tf32(v.y), to_tf32(v.z), to_tf32(v.w));
        }
        __syncthreads();

        if (kt + 1 < nkt) {
            #pragma unroll
            for (int i = 0; i < 4; i++)
                aR[i] = *(const float4*)(Ag + (size_t)(i*32) * K + (kt+1)*BK);
            #pragma unroll
            for (int i = 0; i < 2; i++)
                bR[i] = *(const float4*)(Wg + (size_t)((kt+1)*BK + i*16) * N);
        }

        #pragma unroll
        for (int ks = 0; ks < 4; ks++) {
            unsigned a[2][4];
            #pragma unroll
            for (int mt = 0; mt < 2; mt++) {
                const float* ap = &As[(mwb + mt*16 + g)*ASTR + ks*8 + tig];
                a[mt][0] = __float_as_uint(ap[0]);
                a[mt][1] = __float_as_uint(ap[8*ASTR]);
                a[mt][2] = __float_as_uint(ap[4]);
                a[mt][3] = __float_as_uint(ap[8*ASTR + 4]);
            }
            unsigned b[4][2];
            #pragma unroll
            for (int nt = 0; nt < 4; nt++) {
                const float* bp = &Bs[(ks*8 + tig)*BSTR + nwb + nt*8 + g];
                b[nt][0] = __float_as_uint(bp[0]);
                b[nt][1] = __float_as_uint(bp[4*BSTR]);
            }
            #pragma unroll
            for (int mt = 0; mt < 2; mt++)
                #pragma unroll
                for (int nt = 0; nt < 4; nt++)
                    mma_tf32(d[mt][nt], a[mt], b[nt]);
        }
    }

    #pragma unroll
    for (int mt = 0; mt < 2; mt++) {
        #pragma unroll
        for (int nt = 0; nt < 4; nt++) {
            const int col  = bn0 + nwb + nt*8 + tig*2;
            const float b0 = bias[col], b1 = bias[col + 1];
            const int row0 = bm0 + mwb + mt*16 + g;
            float v0 = d[mt][nt][0] + b0;
            float v1 = d[mt][nt][1] + b1;
            float v2 = d[mt][nt][2] + b0;
            float v3 = d[mt][nt][3] + b1;
            if (DO_GELU) {
                v0 = 0.5f*v0*(1.0f + erff(v0*0.70710678118654752f));
                v1 = 0.5f*v1*(1.0f + erff(v1*0.70710678118654752f));
                v2 = 0.5f*v2*(1.0f + erff(v2*0.70710678118654752f));
                v3 = 0.5f*v3*(1.0f + erff(v3*0.70710678118654752f));
            }
            *(float2*)(C + (size_t)row0 * N + col)       = make_float2(v0, v1);
            *(float2*)(C + (size_t)(row0 + 8) * N + col) = make_float2(v2, v3);
        }
    }
}

// =================== TF32 tensor-core flash attention ===================
// Block: 128 query rows (8 warps x m16), KV tile 32 keys, Dh = 64.
#define BQ  128
#define BKV 32
#define KSTR 68   // K natural [key][d]; B-frag (4g+tig) conflict-free
#define VSTR 36   // V^T [d][key];  B-frag (4g+tig) conflict-free
#define PSTR 36   // P [qrow][key]; A-frag (4g+tig) conflict-free

__global__ void __launch_bounds__(256) attn_tc(
    const float* __restrict__ Q, const float* __restrict__ K,
    const float* __restrict__ V, float* __restrict__ O)
{
    __shared__ float Ks[BKV * KSTR];   //  8704 B
    __shared__ float Vs[HDIM * VSTR];  //  9216 B
    __shared__ float Ps[BQ * PSTR];    // 18432 B

    const int tid  = threadIdx.x;
    const int wid  = tid >> 5, lane = tid & 31;
    const int g    = lane >> 2, tig = lane & 3;
    const int qt = blockIdx.x, h = blockIdx.y, b = blockIdx.z;

    const size_t baseq  = ((size_t)(b*SEQ) + qt*BQ) * EDIM + h*HDIM;
    const size_t basekv = ((size_t)(b*SEQ)) * EDIM + h*HDIM;

    // Q fragments in registers; fold 1/sqrt(Dh) and log2(e) so softmax is pure ex2
    const float qscale = 0.125f * 1.4426950408889634f;
    unsigned qa[8][4];
    {
        const float* qp = Q + baseq + (size_t)(wid*16) * EDIM;
        #pragma unroll
        for (int ks = 0; ks < 8; ks++) {
            const int col = ks*8 + tig;
            qa[ks][0] = tf32u(qp[(size_t)g*EDIM + col] * qscale);
            qa[ks][1] = tf32u(qp[(size_t)(g+8)*EDIM + col] * qscale);
            qa[ks][2] = tf32u(qp[(size_t)g*EDIM + col + 4] * qscale);
            qa[ks][3] = tf32u(qp[(size_t)(g+8)*EDIM + col + 4] * qscale);
        }
    }

    float m0 = -1e30f, m1 = -1e30f, l0 = 0.f, l1 = 0.f;
    float o[8][4];
    #pragma unroll
    for (int nt = 0; nt < 8; nt++)
        #pragma unroll
        for (int j = 0; j < 4; j++) o[nt][j] = 0.f;

    float* Pw = &Ps[(wid*16) * PSTR];   // this warp's private P rows

    for (int t = 0; t < SEQ/BKV; t++) {
        __syncthreads();   // prev tile readers done before overwrite

        // K tile: natural [key][d], float4 stores
        #pragma unroll
        for (int i = 0; i < 2; i++) {
            int fi = tid + i*256;
            int j = fi >> 4, c4 = (fi & 15) * 4;
            float4 kv = *(const float4*)(K + basekv + (size_t)(t*BKV + j)*EDIM + c4);
            *(float4*)&Ks[j*KSTR + c4] =
                make_float4(to_tf32(kv.x), to_tf32(kv.y), to_tf32(kv.z), to_tf32(kv.w));
        }
        // V tile: transposed [d][key]
        #pragma unroll
        for (int i = 0; i < 2; i++) {
            int fi = tid + i*256;
            int w = fi >> 5, kk = (fi >> 3) & 3, cc = fi & 7;
            int j = (w & 7)*4 + kk;
            int c = (w >> 3)*8 + cc;
            float4 vv = *(const float4*)(V + basekv + (size_t)(t*BKV + j)*EDIM + c*4);
            Vs[(c*4+0)*VSTR + j] = to_tf32(vv.x);
            Vs[(c*4+1)*VSTR + j] = to_tf32(vv.y);
            Vs[(c*4+2)*VSTR + j] = to_tf32(vv.z);
            Vs[(c*4+3)*VSTR + j] = to_tf32(vv.w);
        }
        __syncthreads();

        // scores S = Q @ K^T   (m16 x n32, k = 64)
        float s[4][4] = {};
        #pragma unroll
        for (int ks = 0; ks < 8; ks++) {
            #pragma unroll
            for (int nt = 0; nt < 4; nt++) {
                unsigned bf[2];
                const float* bp = &Ks[(nt*8 + g)*KSTR + ks*8 + tig];
                bf[0] = __float_as_uint(bp[0]);
                bf[1] = __float_as_uint(bp[4]);
                mma_tf32(s[nt], qa[ks], bf);
            }
        }

        // online softmax (log2 domain), rows g and g+8
        float rm0 = fmaxf(fmaxf(s[0][0], s[0][1]), fmaxf(s[1][0], s[1][1]));
        rm0 = fmaxf(rm0, fmaxf(fmaxf(s[2][0], s[2][1]), fmaxf(s[3][0], s[3][1])));
        float rm1 = fmaxf(fmaxf(s[0][2], s[0][3]), fmaxf(s[1][2], s[1][3]));
        rm1 = fmaxf(rm1, fmaxf(fmaxf(s[2][2], s[2][3]), fmaxf(s[3][2], s[3][3])));
        #pragma unroll
        for (int off = 1; off < 4; off <<= 1) {
            rm0 = fmaxf(rm0, __shfl_xor_sync(0xffffffffu, rm0, off));
            rm1 = fmaxf(rm1, __shfl_xor_sync(0xffffffffu, rm1, off));
        }
        const float M0 = fmaxf(m0, rm0), M1 = fmaxf(m1, rm1);
        const float a0 = ex2f(m0 - M0), a1 = ex2f(m1 - M1);
        float sum0 = 0.f, sum1 = 0.f;
        #pragma unroll
        for (int nt = 0; nt < 4; nt++) {
            s[nt][0] = ex2f(s[nt][0] - M0);
            s[nt][1] = ex2f(s[nt][1] - M0);
            s[nt][2] = ex2f(s[nt][2] - M1);
            s[nt][3] = ex2f(s[nt][3] - M1);
            sum0 += s[nt][0] + s[nt][1];
            sum1 += s[nt][2] + s[nt][3];
        }
        #pragma unroll
        for (int off = 1; off < 4; off <<= 1) {
            sum0 += __shfl_xor_sync(0xffffffffu, sum0, off);
            sum1 += __shfl_xor_sync(0xffffffffu, sum1, off);
        }
        l0 = l0*a0 + sum0;  l1 = l1*a1 + sum1;
        m0 = M0;            m1 = M1;
        #pragma unroll
        for (int nt = 0; nt < 8; nt++) {
            o[nt][0] *= a0; o[nt][1] *= a0;
            o[nt][2] *= a1; o[nt][3] *= a1;
        }

        // store P (warp-private rows) as tf32
        #pragma unroll
        for (int nt = 0; nt < 4; nt++) {
            *(float2*)&Pw[g*PSTR + nt*8 + 2*tig] =
                make_float2(to_tf32(s[nt][0]), to_tf32(s[nt][1]));
            *(float2*)&Pw[(g+8)*PSTR + nt*8 + 2*tig] =
                make_float2(to_tf32(s[nt][2]), to_tf32(s[nt][3]));
        }
        __syncwarp();

        // O += P @ V   (m16 x n64, k = 32)
        #pragma unroll
        for (int ks = 0; ks < 4; ks++) {
            unsigned pa[4];
            const float* pp = &Pw[g*PSTR + ks*8 + tig];
            pa[0] = __float_as_uint(pp[0]);
            pa[1] = __float_as_uint(pp[8*PSTR]);
            pa[2] = __float_as_uint(pp[4]);
            pa[3] = __float_as_uint(pp[8*PSTR + 4]);
            #pragma unroll
            for (int nt = 0; nt < 8; nt++) {
                unsigned bf[2];
                const float* bp = &Vs[(nt*8 + g)*VSTR + ks*8 + tig];
                bf[0] = __float_as_uint(bp[0]);
                bf[1] = __float_as_uint(bp[4]);
                mma_tf32(o[nt], pa, bf);
            }
        }
    }

    // normalize and store
    const float inv0 = 1.0f / l0, inv1 = 1.0f / l1;
    float* Og = (float*)(O + baseq + (size_t)(wid*16) * EDIM);
    #pragma unroll
    for (int nt = 0; nt < 8; nt++) {
        const int col = nt*8 + 2*tig;
        *(float2*)(Og + (size_t)g*EDIM + col) =
            make_float2(o[nt][0]*inv0, o[nt][1]*inv0);
        *(float2*)(Og + (size_t)(g+8)*EDIM + col) =
            make_float2(o[nt][2]*inv1, o[nt][3]*inv1);
    }
}

// ---------------- fused residual + LayerNorm -------------------------------
__global__ void __launch_bounds__(128) ln_kernel(
    const float* __restrict__ X, const float* __restrict__ Y,
    const float* __restrict__ gamma, const float* __restrict__ beta,
    float* __restrict__ out)
{
    const int row = blockIdx.x;
    const int tid = threadIdx.x;
    const int lane = tid & 31, w = tid >> 5;

    float4 xv = *(const float4*)(X + (size_t)row*EDIM + tid*4);
    float4 yv = *(const float4*)(Y + (size_t)row*EDIM + tid*4);
    float v0 = xv.x + yv.x, v1 = xv.y + yv.y, v2 = xv.z + yv.z, v3 = xv.w + yv.w;

    float sum = v0 + v1 + v2 + v3;
    float sq  = v0*v0 + v1*v1 + v2*v2 + v3*v3;
    #pragma unroll
    for (int off = 16; off > 0; off >>= 1) {
        sum += __shfl_xor_sync(0xffffffffu, sum, off);
        sq  += __shfl_xor_sync(0xffffffffu, sq, off);
    }
    __shared__ float ssum[4], ssq[4];
    if (lane == 0) { ssum[w] = sum; ssq[w] = sq; }
    __syncthreads();
    float ts = ssum[0] + ssum[1] + ssum[2] + ssum[3];
    float tq = ssq[0] + ssq[1] + ssq[2] + ssq[3];

    float mu   = ts * (1.0f/EDIM);
    float var  = tq * (1.0f/EDIM) - mu*mu;
    float rstd = rsqrtf(var + 1e-5f);

    float4 gv = *(const float4*)(gamma + tid*4);
    float4 bv = *(const float4*)(beta  + tid*4);
    float4 ov;
    ov.x = (v0 - mu)*rstd*gv.x + bv.x;
    ov.y = (v1 - mu)*rstd*gv.y + bv.y;
    ov.z = (v2 - mu)*rstd*gv.z + bv.z;
    ov.w = (v3 - mu)*rstd*gv.w + bv.w;
    *(float4*)(out + (size_t)row*EDIM + tid*4) = ov;
}

// ---------------- launch ----------------------------------------------------
extern "C" void kernel_launch(void* const* d_in, const int* in_sizes, int n_in,
                              void* d_out, int out_size)
{
    const float* query = (const float*)d_in[0];
    const float* key   = (const float*)d_in[1];
    const float* value = (const float*)d_in[2];
    const float* Wq = (const float*)d_in[3];  const float* bq = (const float*)d_in[4];
    const float* Wk = (const float*)d_in[5];  const float* bk = (const float*)d_in[6];
    const float* Wv = (const float*)d_in[7];  const float* bv = (const float*)d_in[8];
    const float* Wo = (const float*)d_in[9];  const float* bo = (const float*)d_in[10];
    const float* g1 = (const float*)d_in[11]; const float* be1 = (const float*)d_in[12];
    const float* g2 = (const float*)d_in[13]; const float* be2 = (const float*)d_in[14];
    const float* W1 = (const float*)d_in[15]; const float* b1 = (const float*)d_in[16];
    const float* W2 = (const float*)d_in[17]; const float* b2 = (const float*)d_in[18];
    float* out = (float*)d_out;

    float *q, *k, *v, *ctx, *tmp, *ln1, *hbuf;
    cudaGetSymbolAddress((void**)&q,    g_q);
    cudaGetSymbolAddress((void**)&k,    g_k);
    cudaGetSymbolAddress((void**)&v,    g_v);
    cudaGetSymbolAddress((void**)&ctx,  g_ctx);
    cudaGetSymbolAddress((void**)&tmp,  g_tmp);
    cudaGetSymbolAddress((void**)&ln1,  g_ln1);
    cudaGetSymbolAddress((void**)&hbuf, g_h);

    dim3 gProj(EDIM/BN, MROWS/BM);   // 8 x 64
    dim3 gF1(FFN/BN,  MROWS/BM);     // 32 x 64

    gemm_tc<0><<<gProj, 256>>>(query, Wq, bq, q, MROWS, EDIM, EDIM);
    gemm_tc<0><<<gProj, 256>>>(key,   Wk, bk, k, MROWS, EDIM, EDIM);
    gemm_tc<0><<<gProj, 256>>>(value, Wv, bv, v, MROWS, EDIM, EDIM);

    attn_tc<<<dim3(SEQ/BQ, NH, BATCH), 256>>>(q, k, v, ctx);

    gemm_tc<0><<<gProj, 256>>>(ctx, Wo, bo, tmp, MROWS, EDIM, EDIM);
    ln_kernel<<<MROWS, 128>>>(query, tmp, g1, be1, ln1);

    gemm_tc<1><<<gF1, 256>>>(ln1, W1, b1, hbuf, MROWS, FFN, EDIM);
    gemm_tc<0><<<gProj, 256>>>(hbuf, W2, b2, tmp, MROWS, EDIM, FFN);
    ln_kernel<<<MROWS, 128>>>(ln1, tmp, g2, be2, out);
}

// round 4
// speedup vs baseline: 3.3822x; 1.1272x over previous
#include <cuda_runtime.h>
#include <math.h>

#define EDIM 512
#define HDIM 64
#define NH   8
#define BATCH 4
#define SEQ  2048
#define MROWS (BATCH*SEQ)   // 8192
#define FFN  2048

// ---------------- scratch (no cudaMalloc allowed) ----------------
__device__ float g_q[MROWS*EDIM];
__device__ float g_k[MROWS*EDIM];
__device__ float g_v[MROWS*EDIM];
__device__ float g_ctx[MROWS*EDIM];
__device__ float g_tmp[MROWS*EDIM];
__device__ float g_ln1[MROWS*EDIM];
__device__ float g_h[MROWS*FFN];

// ---------------- common helpers -------------------------------------------
__device__ __forceinline__ float ex2f(float x) {
    float y;
    asm("ex2.approx.ftz.f32 %0, %1;" : "=f"(y) : "f"(x));
    return y;
}
__device__ __forceinline__ void mma_tf32(float d[4],
                                         const unsigned a[4],
                                         const unsigned b[2]) {
    asm volatile(
        "mma.sync.aligned.m16n8k8.row.col.f32.tf32.tf32.f32 "
        "{%0,%1,%2,%3}, {%4,%5,%6,%7}, {%8,%9}, {%0,%1,%2,%3};\n"
        : "+f"(d[0]), "+f"(d[1]), "+f"(d[2]), "+f"(d[3])
        : "r"(a[0]), "r"(a[1]), "r"(a[2]), "r"(a[3]),
          "r"(b[0]), "r"(b[1]));
}
__device__ __forceinline__ void cp16(void* smem, const void* g) {
    unsigned s = (unsigned)__cvta_generic_to_shared(smem);
    asm volatile("cp.async.ca.shared.global [%0], [%1], 16;\n" :: "r"(s), "l"(g));
}
#define CP_COMMIT asm volatile("cp.async.commit_group;\n")
#define CP_WAIT0  asm volatile("cp.async.wait_group 0;\n")

// =================== TF32 tensor-core GEMM (cp.async 2-stage) ===============
// C[M,N] = A[M,K] @ W[K,N] + bias, optional exact GELU.
// Block tile 128x128x16, 256 threads = 8 warps (2m x 4n), warp tile 64x32.
#define GBM 128
#define GBN 128
#define GBK 16
#define GASTR 20    // bank = g*20+tig mod 32 -> permutation, conflict-free
#define GBSTR 136   // bank = tig*8+g        -> permutation, conflict-free

template<int DO_GELU>
__global__ void __launch_bounds__(256) gemm_tc(
    const float* __restrict__ A, const float* __restrict__ W,
    const float* __restrict__ bias, float* __restrict__ C,
    int M, int N, int K)
{
    __shared__ float As[2][GBM * GASTR];   // 2 x 10240 B
    __shared__ float Bs[2][GBK * GBSTR];   // 2 x  8704 B

    const int tid  = threadIdx.x;
    const int wid  = tid >> 5, lane = tid & 31;
    const int g    = lane >> 2, tig = lane & 3;
    const int wm   = wid >> 2,  wn  = wid & 3;
    const int bm0  = blockIdx.y * GBM, bn0 = blockIdx.x * GBN;

    // loaders
    const int ar = tid >> 2,  ac = (tid & 3) * 4;    // A: 64 rows/step, x2
    const int br = tid >> 4,  bc = (tid & 15) * 4;   // B: 16 rows, 64 cols, x2
    const float* Ag = A + (size_t)(bm0 + ar) * K + ac;
    const float* Wg = W + (size_t)br * N + bn0 + bc;

    float d[4][4][4] = {};
    const int nkt = K / GBK;

    // prologue: tile 0 -> buf 0
    cp16(&As[0][ar*GASTR + ac],      Ag);
    cp16(&As[0][(ar+64)*GASTR + ac], Ag + (size_t)64 * K);
    cp16(&Bs[0][br*GBSTR + bc],      Wg);
    cp16(&Bs[0][br*GBSTR + bc + 64], Wg + 64);
    CP_COMMIT;

    for (int kt = 0; kt < nkt; kt++) {
        const int buf = kt & 1;
        CP_WAIT0;
        __syncthreads();

        if (kt + 1 < nkt) {
            const int nb = buf ^ 1;
            const float* An = Ag + (size_t)(kt+1) * GBK;
            const float* Wn = Wg + (size_t)(kt+1) * GBK * N;
            cp16(&As[nb][ar*GASTR + ac],      An);
            cp16(&As[nb][(ar+64)*GASTR + ac], An + (size_t)64 * K);
            cp16(&Bs[nb][br*GBSTR + bc],      Wn);
            cp16(&Bs[nb][br*GBSTR + bc + 64], Wn + 64);
            CP_COMMIT;
        }

        #pragma unroll
        for (int ks = 0; ks < 2; ks++) {
            unsigned a[4][4];
            #pragma unroll
            for (int mt = 0; mt < 4; mt++) {
                const float* ap = &As[buf][(wm*64 + mt*16 + g)*GASTR + ks*8 + tig];
                a[mt][0] = __float_as_uint(ap[0]);
                a[mt][1] = __float_as_uint(ap[8*GASTR]);
                a[mt][2] = __float_as_uint(ap[4]);
                a[mt][3] = __float_as_uint(ap[8*GASTR + 4]);
            }
            unsigned b[4][2];
            #pragma unroll
            for (int nt = 0; nt < 4; nt++) {
                const float* bp = &Bs[buf][(ks*8 + tig)*GBSTR + wn*32 + nt*8 + g];
                b[nt][0] = __float_as_uint(bp[0]);
                b[nt][1] = __float_as_uint(bp[4*GBSTR]);
            }
            #pragma unroll
            for (int mt = 0; mt < 4; mt++)
                #pragma unroll
                for (int nt = 0; nt < 4; nt++)
                    mma_tf32(d[mt][nt], a[mt], b[nt]);
        }
    }

    // epilogue
    #pragma unroll
    for (int mt = 0; mt < 4; mt++) {
        #pragma unroll
        for (int nt = 0; nt < 4; nt++) {
            const int col  = bn0 + wn*32 + nt*8 + tig*2;
            const float b0 = bias[col], b1 = bias[col + 1];
            const int row0 = bm0 + wm*64 + mt*16 + g;
            float v0 = d[mt][nt][0] + b0;
            float v1 = d[mt][nt][1] + b1;
            float v2 = d[mt][nt][2] + b0;
            float v3 = d[mt][nt][3] + b1;
            if (DO_GELU) {
                v0 = 0.5f*v0*(1.0f + erff(v0*0.70710678118654752f));
                v1 = 0.5f*v1*(1.0f + erff(v1*0.70710678118654752f));
                v2 = 0.5f*v2*(1.0f + erff(v2*0.70710678118654752f));
                v3 = 0.5f*v3*(1.0f + erff(v3*0.70710678118654752f));
            }
            *(float2*)(C + (size_t)row0 * N + col)       = make_float2(v0, v1);
            *(float2*)(C + (size_t)(row0 + 8) * N + col) = make_float2(v2, v3);
        }
    }
}

// =================== TF32 tensor-core flash attention ===================
// Block: 128 query rows (8 warps x m16), KV tile 32 keys, Dh = 64.
#define BQ  128
#define BKV 32
#define KSTR 68
#define VSTR 36
#define PSTR 36

__global__ void __launch_bounds__(256) attn_tc(
    const float* __restrict__ Q, const float* __restrict__ K,
    const float* __restrict__ V, float* __restrict__ O)
{
    __shared__ float Ks[BKV * KSTR];
    __shared__ float Vs[HDIM * VSTR];
    __shared__ float Ps[BQ * PSTR];

    const int tid  = threadIdx.x;
    const int wid  = tid >> 5, lane = tid & 31;
    const int g    = lane >> 2, tig = lane & 3;
    const int qt = blockIdx.x, h = blockIdx.y, b = blockIdx.z;

    const size_t baseq  = ((size_t)(b*SEQ) + qt*BQ) * EDIM + h*HDIM;
    const size_t basekv = ((size_t)(b*SEQ)) * EDIM + h*HDIM;

    const float qscale = 0.125f * 1.4426950408889634f;
    unsigned qa[8][4];
    {
        const float* qp = Q + baseq + (size_t)(wid*16) * EDIM;
        #pragma unroll
        for (int ks = 0; ks < 8; ks++) {
            const int col = ks*8 + tig;
            qa[ks][0] = __float_as_uint(qp[(size_t)g*EDIM + col] * qscale);
            qa[ks][1] = __float_as_uint(qp[(size_t)(g+8)*EDIM + col] * qscale);
            qa[ks][2] = __float_as_uint(qp[(size_t)g*EDIM + col + 4] * qscale);
            qa[ks][3] = __float_as_uint(qp[(size_t)(g+8)*EDIM + col + 4] * qscale);
        }
    }

    float m0 = -1e30f, m1 = -1e30f, l0 = 0.f, l1 = 0.f;
    float o[8][4];
    #pragma unroll
    for (int nt = 0; nt < 8; nt++)
        #pragma unroll
        for (int j = 0; j < 4; j++) o[nt][j] = 0.f;

    float* Pw = &Ps[(wid*16) * PSTR];

    for (int t = 0; t < SEQ/BKV; t++) {
        __syncthreads();

        #pragma unroll
        for (int i = 0; i < 2; i++) {
            int fi = tid + i*256;
            int j = fi >> 4, c4 = (fi & 15) * 4;
            *(float4*)&Ks[j*KSTR + c4] =
                *(const float4*)(K + basekv + (size_t)(t*BKV + j)*EDIM + c4);
        }
        #pragma unroll
        for (int i = 0; i < 2; i++) {
            int fi = tid + i*256;
            int w = fi >> 5, kk = (fi >> 3) & 3, cc = fi & 7;
            int j = (w & 7)*4 + kk;
            int c = (w >> 3)*8 + cc;
            float4 vv = *(const float4*)(V + basekv + (size_t)(t*BKV + j)*EDIM + c*4);
            Vs[(c*4+0)*VSTR + j] = vv.x;
            Vs[(c*4+1)*VSTR + j] = vv.y;
            Vs[(c*4+2)*VSTR + j] = vv.z;
            Vs[(c*4+3)*VSTR + j] = vv.w;
        }
        __syncthreads();

        float s[4][4] = {};
        #pragma unroll
        for (int ks = 0; ks < 8; ks++) {
            #pragma unroll
            for (int nt = 0; nt < 4; nt++) {
                unsigned bf[2];
                const float* bp = &Ks[(nt*8 + g)*KSTR + ks*8 + tig];
                bf[0] = __float_as_uint(bp[0]);
                bf[1] = __float_as_uint(bp[4]);
                mma_tf32(s[nt], qa[ks], bf);
            }
        }

        float rm0 = fmaxf(fmaxf(s[0][0], s[0][1]), fmaxf(s[1][0], s[1][1]));
        rm0 = fmaxf(rm0, fmaxf(fmaxf(s[2][0], s[2][1]), fmaxf(s[3][0], s[3][1])));
        float rm1 = fmaxf(fmaxf(s[0][2], s[0][3]), fmaxf(s[1][2], s[1][3]));
        rm1 = fmaxf(rm1, fmaxf(fmaxf(s[2][2], s[2][3]), fmaxf(s[3][2], s[3][3])));
        #pragma unroll
        for (int off = 1; off < 4; off <<= 1) {
            rm0 = fmaxf(rm0, __shfl_xor_sync(0xffffffffu, rm0, off));
            rm1 = fmaxf(rm1, __shfl_xor_sync(0xffffffffu, rm1, off));
        }
        const float M0 = fmaxf(m0, rm0), M1 = fmaxf(m1, rm1);
        const float a0 = ex2f(m0 - M0), a1 = ex2f(m1 - M1);
        float sum0 = 0.f, sum1 = 0.f;
        #pragma unroll
        for (int nt = 0; nt < 4; nt++) {
            s[nt][0] = ex2f(s[nt][0] - M0);
            s[nt][1] = ex2f(s[nt][1] - M0);
            s[nt][2] = ex2f(s[nt][2] - M1);
            s[nt][3] = ex2f(s[nt][3] - M1);
            sum0 += s[nt][0] + s[nt][1];
            sum1 += s[nt][2] + s[nt][3];
        }
        #pragma unroll
        for (int off = 1; off < 4; off <<= 1) {
            sum0 += __shfl_xor_sync(0xffffffffu, sum0, off);
            sum1 += __shfl_xor_sync(0xffffffffu, sum1, off);
        }
        l0 = l0*a0 + sum0;  l1 = l1*a1 + sum1;
        m0 = M0;            m1 = M1;
        #pragma unroll
        for (int nt = 0; nt < 8; nt++) {
            o[nt][0] *= a0; o[nt][1] *= a0;
            o[nt][2] *= a1; o[nt][3] *= a1;
        }

        #pragma unroll
        for (int nt = 0; nt < 4; nt++) {
            *(float2*)&Pw[g*PSTR + nt*8 + 2*tig]     = make_float2(s[nt][0], s[nt][1]);
            *(float2*)&Pw[(g+8)*PSTR + nt*8 + 2*tig] = make_float2(s[nt][2], s[nt][3]);
        }
        __syncwarp();

        #pragma unroll
        for (int ks = 0; ks < 4; ks++) {
            unsigned pa[4];
            const float* pp = &Pw[g*PSTR + ks*8 + tig];
            pa[0] = __float_as_uint(pp[0]);
            pa[1] = __float_as_uint(pp[8*PSTR]);
            pa[2] = __float_as_uint(pp[4]);
            pa[3] = __float_as_uint(pp[8*PSTR + 4]);
            #pragma unroll
            for (int nt = 0; nt < 8; nt++) {
                unsigned bf[2];
                const float* bp = &Vs[(nt*8 + g)*VSTR + ks*8 + tig];
                bf[0] = __float_as_uint(bp[0]);
                bf[1] = __float_as_uint(bp[4]);
                mma_tf32(o[nt], pa, bf);
            }
        }
    }

    const float inv0 = 1.0f / l0, inv1 = 1.0f / l1;
    float* Og = (float*)(O + baseq + (size_t)(wid*16) * EDIM);
    #pragma unroll
    for (int nt = 0; nt < 8; nt++) {
        const int col = nt*8 + 2*tig;
        *(float2*)(Og + (size_t)g*EDIM + col) =
            make_float2(o[nt][0]*inv0, o[nt][1]*inv0);
        *(float2*)(Og + (size_t)(g+8)*EDIM + col) =
            make_float2(o[nt][2]*inv1, o[nt][3]*inv1);
    }
}

// ---------------- fused residual + LayerNorm -------------------------------
__global__ void __launch_bounds__(128) ln_kernel(
    const float* __restrict__ X, const float* __restrict__ Y,
    const float* __restrict__ gamma, const float* __restrict__ beta,
    float* __restrict__ out)
{
    const int row = blockIdx.x;
    const int tid = threadIdx.x;
    const int lane = tid & 31, w = tid >> 5;

    float4 xv = *(const float4*)(X + (size_t)row*EDIM + tid*4);
    float4 yv = *(const float4*)(Y + (size_t)row*EDIM + tid*4);
    float v0 = xv.x + yv.x, v1 = xv.y + yv.y, v2 = xv.z + yv.z, v3 = xv.w + yv.w;

    float sum = v0 + v1 + v2 + v3;
    float sq  = v0*v0 + v1*v1 + v2*v2 + v3*v3;
    #pragma unroll
    for (int off = 16; off > 0; off >>= 1) {
        sum += __shfl_xor_sync(0xffffffffu, sum, off);
        sq  += __shfl_xor_sync(0xffffffffu, sq, off);
    }
    __shared__ float ssum[4], ssq[4];
    if (lane == 0) { ssum[w] = sum; ssq[w] = sq; }
    __syncthreads();
    float ts = ssum[0] + ssum[1] + ssum[2] + ssum[3];
    float tq = ssq[0] + ssq[1] + ssq[2] + ssq[3];

    float mu   = ts * (1.0f/EDIM);
    float var  = tq * (1.0f/EDIM) - mu*mu;
    float rstd = rsqrtf(var + 1e-5f);

    float4 gv = *(const float4*)(gamma + tid*4);
    float4 bv = *(const float4*)(beta  + tid*4);
    float4 ov;
    ov.x = (v0 - mu)*rstd*gv.x + bv.x;
    ov.y = (v1 - mu)*rstd*gv.y + bv.y;
    ov.z = (v2 - mu)*rstd*gv.z + bv.z;
    ov.w = (v3 - mu)*rstd*gv.w + bv.w;
    *(float4*)(out + (size_t)row*EDIM + tid*4) = ov;
}

// ---------------- launch ----------------------------------------------------
extern "C" void kernel_launch(void* const* d_in, const int* in_sizes, int n_in,
                              void* d_out, int out_size)
{
    const float* query = (const float*)d_in[0];
    const float* key   = (const float*)d_in[1];
    const float* value = (const float*)d_in[2];
    const float* Wq = (const float*)d_in[3];  const float* bq = (const float*)d_in[4];
    const float* Wk = (const float*)d_in[5];  const float* bk = (const float*)d_in[6];
    const float* Wv = (const float*)d_in[7];  const float* bv = (const float*)d_in[8];
    const float* Wo = (const float*)d_in[9];  const float* bo = (const float*)d_in[10];
    const float* g1 = (const float*)d_in[11]; const float* be1 = (const float*)d_in[12];
    const float* g2 = (const float*)d_in[13]; const float* be2 = (const float*)d_in[14];
    const float* W1 = (const float*)d_in[15]; const float* b1 = (const float*)d_in[16];
    const float* W2 = (const float*)d_in[17]; const float* b2 = (const float*)d_in[18];
    float* out = (float*)d_out;

    float *q, *k, *v, *ctx, *tmp, *ln1, *hbuf;
    cudaGetSymbolAddress((void**)&q,    g_q);
    cudaGetSymbolAddress((void**)&k,    g_k);
    cudaGetSymbolAddress((void**)&v,    g_v);
    cudaGetSymbolAddress((void**)&ctx,  g_ctx);
    cudaGetSymbolAddress((void**)&tmp,  g_tmp);
    cudaGetSymbolAddress((void**)&ln1,  g_ln1);
    cudaGetSymbolAddress((void**)&hbuf, g_h);

    dim3 gProj(EDIM/GBN, MROWS/GBM);   // 4 x 64
    dim3 gF1(FFN/GBN,  MROWS/GBM);     // 16 x 64

    gemm_tc<0><<<gProj, 256>>>(query, Wq, bq, q, MROWS, EDIM, EDIM);
    gemm_tc<0><<<gProj, 256>>>(key,   Wk, bk, k, MROWS, EDIM, EDIM);
    gemm_tc<0><<<gProj, 256>>>(value, Wv, bv, v, MROWS, EDIM, EDIM);

    attn_tc<<<dim3(SEQ/BQ, NH, BATCH), 256>>>(q, k, v, ctx);

    gemm_tc<0><<<gProj, 256>>>(ctx, Wo, bo, tmp, MROWS, EDIM, EDIM);
    ln_kernel<<<MROWS, 128>>>(query, tmp, g1, be1, ln1);

    gemm_tc<1><<<gF1, 256>>>(ln1, W1, b1, hbuf, MROWS, FFN, EDIM);
    gemm_tc<0><<<gProj, 256>>>(hbuf, W2, b2, tmp, MROWS, EDIM, FFN);
    ln_kernel<<<MROWS, 128>>>(ln1, tmp, g2, be2, out);
}

// round 5
// speedup vs baseline: 3.4766x; 1.0279x over previous
#include <cuda_runtime.h>
#include <math.h>

#define EDIM 512
#define HDIM 64
#define NH   8
#define BATCH 4
#define SEQ  2048
#define MROWS (BATCH*SEQ)   // 8192
#define FFN  2048

// ---------------- scratch (no cudaMalloc allowed) ----------------
__device__ float g_q[MROWS*EDIM];
__device__ float g_k[MROWS*EDIM];
__device__ float g_v[MROWS*EDIM];
__device__ float g_ctx[MROWS*EDIM];
__device__ float g_tmp[MROWS*EDIM];
__device__ float g_ln1[MROWS*EDIM];
__device__ float g_h[MROWS*FFN];

// ---------------- common helpers -------------------------------------------
__device__ __forceinline__ float ex2f(float x) {
    float y;
    asm("ex2.approx.ftz.f32 %0, %1;" : "=f"(y) : "f"(x));
    return y;
}
__device__ __forceinline__ void mma_tf32(float d[4],
                                         const unsigned a[4],
                                         const unsigned b[2]) {
    asm volatile(
        "mma.sync.aligned.m16n8k8.row.col.f32.tf32.tf32.f32 "
        "{%0,%1,%2,%3}, {%4,%5,%6,%7}, {%8,%9}, {%0,%1,%2,%3};\n"
        : "+f"(d[0]), "+f"(d[1]), "+f"(d[2]), "+f"(d[3])
        : "r"(a[0]), "r"(a[1]), "r"(a[2]), "r"(a[3]),
          "r"(b[0]), "r"(b[1]));
}
__device__ __forceinline__ void cp16(void* smem, const void* g) {
    unsigned s = (unsigned)__cvta_generic_to_shared(smem);
    asm volatile("cp.async.ca.shared.global [%0], [%1], 16;\n" :: "r"(s), "l"(g));
}
#define CP_COMMIT asm volatile("cp.async.commit_group;\n")
#define CP_WAIT0  asm volatile("cp.async.wait_group 0;\n")

// =================== TF32 tensor-core GEMM (cp.async 2-stage, BK=32) ========
#define GBM 128
#define GBN 128
#define GBK 32
#define GASTR 36    // bank = (g*36+tig)%32 = 4g+tig -> permutation
#define GBSTR 136   // bank = (tig*136+g)%32 = 8tig+g -> permutation
#define GEMM_SMEM ((2*GBM*GASTR + 2*GBK*GBSTR) * 4)   // 71680 B

template<int DO_GELU>
__global__ void __launch_bounds__(256, 2) gemm_tc(
    const float* __restrict__ A, const float* __restrict__ W,
    const float* __restrict__ bias, float* __restrict__ C,
    int M, int N, int K)
{
    extern __shared__ float sm[];
    float* As = sm;                       // [2][GBM*GASTR]
    float* Bs = sm + 2*GBM*GASTR;         // [2][GBK*GBSTR]

    const int tid  = threadIdx.x;
    const int wid  = tid >> 5, lane = tid & 31;
    const int g    = lane >> 2, tig = lane & 3;
    const int wm   = wid >> 2,  wn  = wid & 3;
    const int bm0  = blockIdx.y * GBM, bn0 = blockIdx.x * GBN;

    // loaders: A 128x32 (1024 f4), B 32x128 (1024 f4) -> 4 cp16 each per tile
    const int ar = tid >> 2,  ac = (tid & 3) * 4;
    const int br = tid >> 4,  bc = (tid & 15) * 4;
    const float* Ag = A + (size_t)(bm0 + ar) * K + ac;
    const float* Wg = W + (size_t)br * N + bn0 + bc;

    float d[4][4][4] = {};
    const int nkt = K / GBK;

    // prologue
    cp16(&As[ar*GASTR + ac],           Ag);
    cp16(&As[ar*GASTR + ac + 16],      Ag + 16);
    cp16(&As[(ar+64)*GASTR + ac],      Ag + (size_t)64 * K);
    cp16(&As[(ar+64)*GASTR + ac + 16], Ag + (size_t)64 * K + 16);
    cp16(&Bs[br*GBSTR + bc],           Wg);
    cp16(&Bs[br*GBSTR + bc + 64],      Wg + 64);
    cp16(&Bs[(br+16)*GBSTR + bc],      Wg + (size_t)16 * N);
    cp16(&Bs[(br+16)*GBSTR + bc + 64], Wg + (size_t)16 * N + 64);
    CP_COMMIT;

    for (int kt = 0; kt < nkt; kt++) {
        const int buf = kt & 1;
        float* Ab = As + buf * (GBM*GASTR);
        float* Bb = Bs + buf * (GBK*GBSTR);
        CP_WAIT0;
        __syncthreads();

        if (kt + 1 < nkt) {
            float* An_ = As + (buf^1) * (GBM*GASTR);
            float* Bn_ = Bs + (buf^1) * (GBK*GBSTR);
            const float* Agn = Ag + (size_t)(kt+1) * GBK;
            const float* Wgn = Wg + (size_t)(kt+1) * GBK * N;
            cp16(&An_[ar*GASTR + ac],           Agn);
            cp16(&An_[ar*GASTR + ac + 16],      Agn + 16);
            cp16(&An_[(ar+64)*GASTR + ac],      Agn + (size_t)64 * K);
            cp16(&An_[(ar+64)*GASTR + ac + 16], Agn + (size_t)64 * K + 16);
            cp16(&Bn_[br*GBSTR + bc],           Wgn);
            cp16(&Bn_[br*GBSTR + bc + 64],      Wgn + 64);
            cp16(&Bn_[(br+16)*GBSTR + bc],      Wgn + (size_t)16 * N);
            cp16(&Bn_[(br+16)*GBSTR + bc + 64], Wgn + (size_t)16 * N + 64);
            CP_COMMIT;
        }

        #pragma unroll
        for (int ks = 0; ks < 4; ks++) {
            unsigned a[4][4];
            #pragma unroll
            for (int mt = 0; mt < 4; mt++) {
                const float* ap = &Ab[(wm*64 + mt*16 + g)*GASTR + ks*8 + tig];
                a[mt][0] = __float_as_uint(ap[0]);
                a[mt][1] = __float_as_uint(ap[8*GASTR]);
                a[mt][2] = __float_as_uint(ap[4]);
                a[mt][3] = __float_as_uint(ap[8*GASTR + 4]);
            }
            unsigned b[4][2];
            #pragma unroll
            for (int nt = 0; nt < 4; nt++) {
                const float* bp = &Bb[(ks*8 + tig)*GBSTR + wn*32 + nt*8 + g];
                b[nt][0] = __float_as_uint(bp[0]);
                b[nt][1] = __float_as_uint(bp[4*GBSTR]);
            }
            #pragma unroll
            for (int mt = 0; mt < 4; mt++)
                #pragma unroll
                for (int nt = 0; nt < 4; nt++)
                    mma_tf32(d[mt][nt], a[mt], b[nt]);
        }
    }

    #pragma unroll
    for (int mt = 0; mt < 4; mt++) {
        #pragma unroll
        for (int nt = 0; nt < 4; nt++) {
            const int col  = bn0 + wn*32 + nt*8 + tig*2;
            const float b0 = bias[col], b1 = bias[col + 1];
            const int row0 = bm0 + wm*64 + mt*16 + g;
            float v0 = d[mt][nt][0] + b0;
            float v1 = d[mt][nt][1] + b1;
            float v2 = d[mt][nt][2] + b0;
            float v3 = d[mt][nt][3] + b1;
            if (DO_GELU) {
                v0 = 0.5f*v0*(1.0f + erff(v0*0.70710678118654752f));
                v1 = 0.5f*v1*(1.0f + erff(v1*0.70710678118654752f));
                v2 = 0.5f*v2*(1.0f + erff(v2*0.70710678118654752f));
                v3 = 0.5f*v3*(1.0f + erff(v3*0.70710678118654752f));
            }
            *(float2*)(C + (size_t)row0 * N + col)       = make_float2(v0, v1);
            *(float2*)(C + (size_t)(row0 + 8) * N + col) = make_float2(v2, v3);
        }
    }
}

// =================== TF32 flash attention (BKV=64, cp.async 2-stage) ========
#define BQ  128
#define BKV 64
#define KSTR 68   // QK B-frag: (4g+tig) permutation
#define VSTR 72   // PV B-frag: (8tig+g) permutation (V natural [key][d])
#define PSTR 68   // PV A-frag: (4g+tig) permutation
#define KBUF (BKV*KSTR)
#define VBUF (BKV*VSTR)
#define ATTN_SMEM ((2*KBUF + 2*VBUF + BQ*PSTR) * 4)   // 106496 B

__global__ void __launch_bounds__(256, 2) attn_tc(
    const float* __restrict__ Q, const float* __restrict__ K,
    const float* __restrict__ V, float* __restrict__ O)
{
    extern __shared__ float sm[];
    float* Ks = sm;                    // [2][KBUF]
    float* Vs = sm + 2*KBUF;           // [2][VBUF]
    float* Ps = sm + 2*KBUF + 2*VBUF;  // [BQ*PSTR]

    const int tid  = threadIdx.x;
    const int wid  = tid >> 5, lane = tid & 31;
    const int g    = lane >> 2, tig = lane & 3;
    const int qt = blockIdx.x, h = blockIdx.y, b = blockIdx.z;

    const size_t baseq  = ((size_t)(b*SEQ) + qt*BQ) * EDIM + h*HDIM;
    const size_t basekv = ((size_t)(b*SEQ)) * EDIM + h*HDIM;

    const float qscale = 0.125f * 1.4426950408889634f;
    unsigned qa[8][4];
    {
        const float* qp = Q + baseq + (size_t)(wid*16) * EDIM;
        #pragma unroll
        for (int ks = 0; ks < 8; ks++) {
            const int col = ks*8 + tig;
            qa[ks][0] = __float_as_uint(qp[(size_t)g*EDIM + col] * qscale);
            qa[ks][1] = __float_as_uint(qp[(size_t)(g+8)*EDIM + col] * qscale);
            qa[ks][2] = __float_as_uint(qp[(size_t)g*EDIM + col + 4] * qscale);
            qa[ks][3] = __float_as_uint(qp[(size_t)(g+8)*EDIM + col + 4] * qscale);
        }
    }

    float m0 = -1e30f, m1 = -1e30f, l0 = 0.f, l1 = 0.f;
    float o[8][4];
    #pragma unroll
    for (int nt = 0; nt < 8; nt++)
        #pragma unroll
        for (int j = 0; j < 4; j++) o[nt][j] = 0.f;

    float* Pw = &Ps[(wid*16) * PSTR];

    // KV tile loader: thread -> key row j = tid>>2, 4 col-blocks of 16B
    const int lj = tid >> 2, lc = (tid & 3) * 4;
    const float* Kg0 = K + basekv + (size_t)lj * EDIM + lc;
    const float* Vg0 = V + basekv + (size_t)lj * EDIM + lc;
    const int nTiles = SEQ / BKV;

    // prologue: tile 0 -> buf 0
    #pragma unroll
    for (int i = 0; i < 4; i++) {
        cp16(&Ks[lj*KSTR + lc + i*16], Kg0 + i*16);
        cp16(&Vs[lj*VSTR + lc + i*16], Vg0 + i*16);
    }
    CP_COMMIT;

    for (int t = 0; t < nTiles; t++) {
        const int buf = t & 1;
        const float* Kb = Ks + buf * KBUF;
        const float* Vb = Vs + buf * VBUF;
        CP_WAIT0;
        __syncthreads();

        if (t + 1 < nTiles) {
            float* Kn = Ks + (buf^1) * KBUF;
            float* Vn = Vs + (buf^1) * VBUF;
            const size_t off = (size_t)(t+1) * BKV * EDIM;
            #pragma unroll
            for (int i = 0; i < 4; i++) {
                cp16(&Kn[lj*KSTR + lc + i*16], Kg0 + off + i*16);
                cp16(&Vn[lj*VSTR + lc + i*16], Vg0 + off + i*16);
            }
            CP_COMMIT;
        }

        // S = Q @ K^T  (m16 x n64, k=64)
        float s[8][4];
        #pragma unroll
        for (int nt = 0; nt < 8; nt++)
            #pragma unroll
            for (int j = 0; j < 4; j++) s[nt][j] = 0.f;
        #pragma unroll
        for (int ks = 0; ks < 8; ks++) {
            #pragma unroll
            for (int nt = 0; nt < 8; nt++) {
                unsigned bf[2];
                const float* bp = &Kb[(nt*8 + g)*KSTR + ks*8 + tig];
                bf[0] = __float_as_uint(bp[0]);
                bf[1] = __float_as_uint(bp[4]);
                mma_tf32(s[nt], qa[ks], bf);
            }
        }

        // online softmax over 64 keys, rows g (lo) and g+8 (hi)
        float rm0 = -1e30f, rm1 = -1e30f;
        #pragma unroll
        for (int nt = 0; nt < 8; nt++) {
            rm0 = fmaxf(rm0, fmaxf(s[nt][0], s[nt][1]));
            rm1 = fmaxf(rm1, fmaxf(s[nt][2], s[nt][3]));
        }
        #pragma unroll
        for (int off = 1; off < 4; off <<= 1) {
            rm0 = fmaxf(rm0, __shfl_xor_sync(0xffffffffu, rm0, off));
            rm1 = fmaxf(rm1, __shfl_xor_sync(0xffffffffu, rm1, off));
        }
        const float M0 = fmaxf(m0, rm0), M1 = fmaxf(m1, rm1);
        const float a0 = ex2f(m0 - M0), a1 = ex2f(m1 - M1);
        float sum0 = 0.f, sum1 = 0.f;
        #pragma unroll
        for (int nt = 0; nt < 8; nt++) {
            s[nt][0] = ex2f(s[nt][0] - M0);
            s[nt][1] = ex2f(s[nt][1] - M0);
            s[nt][2] = ex2f(s[nt][2] - M1);
            s[nt][3] = ex2f(s[nt][3] - M1);
            sum0 += s[nt][0] + s[nt][1];
            sum1 += s[nt][2] + s[nt][3];
        }
        #pragma unroll
        for (int off = 1; off < 4; off <<= 1) {
            sum0 += __shfl_xor_sync(0xffffffffu, sum0, off);
            sum1 += __shfl_xor_sync(0xffffffffu, sum1, off);
        }
        l0 = l0*a0 + sum0;  l1 = l1*a1 + sum1;
        m0 = M0;            m1 = M1;
        #pragma unroll
        for (int nt = 0; nt < 8; nt++) {
            o[nt][0] *= a0; o[nt][1] *= a0;
            o[nt][2] *= a1; o[nt][3] *= a1;
        }

        // store P (warp-private rows)
        #pragma unroll
        for (int nt = 0; nt < 8; nt++) {
            *(float2*)&Pw[g*PSTR + nt*8 + 2*tig]     = make_float2(s[nt][0], s[nt][1]);
            *(float2*)&Pw[(g+8)*PSTR + nt*8 + 2*tig] = make_float2(s[nt][2], s[nt][3]);
        }
        __syncwarp();

        // O += P @ V  (m16 x n64, k=64), V natural [key][d]
        #pragma unroll
        for (int ks = 0; ks < 8; ks++) {
            unsigned pa[4];
            const float* pp = &Pw[g*PSTR + ks*8 + tig];
            pa[0] = __float_as_uint(pp[0]);
            pa[1] = __float_as_uint(pp[8*PSTR]);
            pa[2] = __float_as_uint(pp[4]);
            pa[3] = __float_as_uint(pp[8*PSTR + 4]);
            #pragma unroll
            for (int nt = 0; nt < 8; nt++) {
                unsigned bf[2];
                const float* bp = &Vb[(ks*8 + tig)*VSTR + nt*8 + g];
                bf[0] = __float_as_uint(bp[0]);
                bf[1] = __float_as_uint(bp[4*VSTR]);
                mma_tf32(o[nt], pa, bf);
            }
        }
    }

    const float inv0 = 1.0f / l0, inv1 = 1.0f / l1;
    float* Og = (float*)(O + baseq + (size_t)(wid*16) * EDIM);
    #pragma unroll
    for (int nt = 0; nt < 8; nt++) {
        const int col = nt*8 + 2*tig;
        *(float2*)(Og + (size_t)g*EDIM + col) =
            make_float2(o[nt][0]*inv0, o[nt][1]*inv0);
        *(float2*)(Og + (size_t)(g+8)*EDIM + col) =
            make_float2(o[nt][2]*inv1, o[nt][3]*inv1);
    }
}

// ---------------- fused residual + LayerNorm (warp per row) -----------------
__global__ void __launch_bounds__(256) ln_kernel(
    const float* __restrict__ X, const float* __restrict__ Y,
    const float* __restrict__ gamma, const float* __restrict__ beta,
    float* __restrict__ out)
{
    const int lane = threadIdx.x & 31;
    const int row  = blockIdx.x * 8 + (threadIdx.x >> 5);

    float4 v[4];
    float sum = 0.f, sq = 0.f;
    #pragma unroll
    for (int i = 0; i < 4; i++) {
        const int c = (i*32 + lane) * 4;
        float4 xv = *(const float4*)(X + (size_t)row*EDIM + c);
        float4 yv = *(const float4*)(Y + (size_t)row*EDIM + c);
        v[i].x = xv.x + yv.x; v[i].y = xv.y + yv.y;
        v[i].z = xv.z + yv.z; v[i].w = xv.w + yv.w;
        sum += v[i].x + v[i].y + v[i].z + v[i].w;
        sq  += v[i].x*v[i].x + v[i].y*v[i].y + v[i].z*v[i].z + v[i].w*v[i].w;
    }
    #pragma unroll
    for (int off = 16; off > 0; off >>= 1) {
        sum += __shfl_xor_sync(0xffffffffu, sum, off);
        sq  += __shfl_xor_sync(0xffffffffu, sq, off);
    }
    const float mu   = sum * (1.0f/EDIM);
    const float var  = sq * (1.0f/EDIM) - mu*mu;
    const float rstd = rsqrtf(var + 1e-5f);

    #pragma unroll
    for (int i = 0; i < 4; i++) {
        const int c = (i*32 + lane) * 4;
        float4 gv = *(const float4*)(gamma + c);
        float4 bv = *(const float4*)(beta  + c);
        float4 ov;
        ov.x = (v[i].x - mu)*rstd*gv.x + bv.x;
        ov.y = (v[i].y - mu)*rstd*gv.y + bv.y;
        ov.z = (v[i].z - mu)*rstd*gv.z + bv.z;
        ov.w = (v[i].w - mu)*rstd*gv.w + bv.w;
        *(float4*)(out + (size_t)row*EDIM + c) = ov;
    }
}

// ---------------- launch ----------------------------------------------------
extern "C" void kernel_launch(void* const* d_in, const int* in_sizes, int n_in,
                              void* d_out, int out_size)
{
    const float* query = (const float*)d_in[0];
    const float* key   = (const float*)d_in[1];
    const float* value = (const float*)d_in[2];
    const float* Wq = (const float*)d_in[3];  const float* bq = (const float*)d_in[4];
    const float* Wk = (const float*)d_in[5];  const float* bk = (const float*)d_in[6];
    const float* Wv = (const float*)d_in[7];  const float* bv = (const float*)d_in[8];
    const float* Wo = (const float*)d_in[9];  const float* bo = (const float*)d_in[10];
    const float* g1 = (const float*)d_in[11]; const float* be1 = (const float*)d_in[12];
    const float* g2 = (const float*)d_in[13]; const float* be2 = (const float*)d_in[14];
    const float* W1 = (const float*)d_in[15]; const float* b1 = (const float*)d_in[16];
    const float* W2 = (const float*)d_in[17]; const float* b2 = (const float*)d_in[18];
    float* out = (float*)d_out;

    float *q, *k, *v, *ctx, *tmp, *ln1, *hbuf;
    cudaGetSymbolAddress((void**)&q,    g_q);
    cudaGetSymbolAddress((void**)&k,    g_k);
    cudaGetSymbolAddress((void**)&v,    g_v);
    cudaGetSymbolAddress((void**)&ctx,  g_ctx);
    cudaGetSymbolAddress((void**)&tmp,  g_tmp);
    cudaGetSymbolAddress((void**)&ln1,  g_ln1);
    cudaGetSymbolAddress((void**)&hbuf, g_h);

    cudaFuncSetAttribute(gemm_tc<0>, cudaFuncAttributeMaxDynamicSharedMemorySize, GEMM_SMEM);
    cudaFuncSetAttribute(gemm_tc<1>, cudaFuncAttributeMaxDynamicSharedMemorySize, GEMM_SMEM);
    cudaFuncSetAttribute(attn_tc,    cudaFuncAttributeMaxDynamicSharedMemorySize, ATTN_SMEM);

    dim3 gProj(EDIM/GBN, MROWS/GBM);   // 4 x 64
    dim3 gF1(FFN/GBN,  MROWS/GBM);     // 16 x 64

    gemm_tc<0><<<gProj, 256, GEMM_SMEM>>>(query, Wq, bq, q, MROWS, EDIM, EDIM);
    gemm_tc<0><<<gProj, 256, GEMM_SMEM>>>(key,   Wk, bk, k, MROWS, EDIM, EDIM);
    gemm_tc<0><<<gProj, 256, GEMM_SMEM>>>(value, Wv, bv, v, MROWS, EDIM, EDIM);

    attn_tc<<<dim3(SEQ/BQ, NH, BATCH), 256, ATTN_SMEM>>>(q, k, v, ctx);

    gemm_tc<0><<<gProj, 256, GEMM_SMEM>>>(ctx, Wo, bo, tmp, MROWS, EDIM, EDIM);
    ln_kernel<<<MROWS/8, 256>>>(query, tmp, g1, be1, ln1);

    gemm_tc<1><<<gF1, 256, GEMM_SMEM>>>(ln1, W1, b1, hbuf, MROWS, FFN, EDIM);
    gemm_tc<0><<<gProj, 256, GEMM_SMEM>>>(hbuf, W2, b2, tmp, MROWS, EDIM, FFN);
    ln_kernel<<<MROWS/8, 256>>>(ln1, tmp, g2, be2, out);
}